// round 1
// baseline (speedup 1.0000x reference)
#include <cuda_runtime.h>
#include <math.h>

// Problem dims
#define NTOK 4096          // B*S
#define EDIM 1024
#define CDIM 1024
#define HDIM 4096
#define VDIM 32000
#define EPS_LN 1e-5f

// ---------------------------------------------------------------------------
// Scratch (static device globals; no allocation anywhere)
// ---------------------------------------------------------------------------
__device__ float g_x[NTOK * EDIM];          // LN(embed)
__device__ float g_cat[NTOK * (EDIM + CDIM)];
__device__ float g_h1[NTOK * HDIM];
__device__ float g_h2[NTOK * HDIM];
__device__ float g_ctx[NTOK * CDIM];
__device__ float g_dl[NTOK * CDIM];
__device__ float g_fg[NTOK * CDIM];
__device__ float g_ig[NTOK * CDIM];

// ---------------------------------------------------------------------------
// Block-wide sum over 256 threads
// ---------------------------------------------------------------------------
__device__ __forceinline__ float block_sum256(float val) {
    __shared__ float sh[8];
    int lane = threadIdx.x & 31;
    #pragma unroll
    for (int o = 16; o > 0; o >>= 1)
        val += __shfl_xor_sync(0xffffffffu, val, o);
    if (lane == 0) sh[threadIdx.x >> 5] = val;
    __syncthreads();
    float t = (lane < 8) ? sh[lane] : 0.f;
    #pragma unroll
    for (int o = 4; o > 0; o >>= 1)
        t += __shfl_xor_sync(0xffffffffu, t, o);
    t = __shfl_sync(0xffffffffu, t, 0);
    __syncthreads();   // protect sh for a subsequent call
    return t;
}

// ---------------------------------------------------------------------------
// Embedding gather + LayerNorm. 1 block per token, 256 threads, 4 elems each.
// ---------------------------------------------------------------------------
__global__ void embed_ln_kernel(const int* __restrict__ ids,
                                const float* __restrict__ tbl,
                                const float* __restrict__ gw,
                                const float* __restrict__ gb) {
    int row = blockIdx.x;
    size_t base = (size_t)ids[row] * EDIM;
    float v[4];
    float s = 0.f;
    #pragma unroll
    for (int i = 0; i < 4; i++) {
        v[i] = tbl[base + threadIdx.x + i * 256];
        s += v[i];
    }
    float mean = block_sum256(s) * (1.f / (float)EDIM);
    float s2 = 0.f;
    #pragma unroll
    for (int i = 0; i < 4; i++) { float d = v[i] - mean; s2 += d * d; }
    float rstd = rsqrtf(block_sum256(s2) * (1.f / (float)EDIM) + EPS_LN);
    #pragma unroll
    for (int i = 0; i < 4; i++) {
        int c = threadIdx.x + i * 256;
        g_x[(size_t)row * EDIM + c] = (v[i] - mean) * rstd * gw[c] + gb[c];
    }
}

// ---------------------------------------------------------------------------
// ctx = LN(f*ctx + i*delta) per row
// ---------------------------------------------------------------------------
__global__ void ctx_update_kernel(const float* __restrict__ cg,
                                  const float* __restrict__ cb) {
    int row = blockIdx.x;
    size_t b = (size_t)row * CDIM;
    float v[4];
    float s = 0.f;
    #pragma unroll
    for (int i = 0; i < 4; i++) {
        int c = threadIdx.x + i * 256;
        v[i] = g_fg[b + c] * g_ctx[b + c] + g_ig[b + c] * g_dl[b + c];
        s += v[i];
    }
    float mean = block_sum256(s) * (1.f / (float)CDIM);
    float s2 = 0.f;
    #pragma unroll
    for (int i = 0; i < 4; i++) { float d = v[i] - mean; s2 += d * d; }
    float rstd = rsqrtf(block_sum256(s2) * (1.f / (float)CDIM) + EPS_LN);
    #pragma unroll
    for (int i = 0; i < 4; i++) {
        int c = threadIdx.x + i * 256;
        g_ctx[b + c] = (v[i] - mean) * rstd * cg[c] + cb[c];
    }
}

// ---------------------------------------------------------------------------
// Zero ctx (ctx re-initialized to zero every forward)
// grid = NTOK*CDIM/4/256 = 4096 blocks
// ---------------------------------------------------------------------------
__global__ void zero_ctx_kernel() {
    int i = blockIdx.x * blockDim.x + threadIdx.x;
    ((float4*)g_ctx)[i] = make_float4(0.f, 0.f, 0.f, 0.f);
}

// ---------------------------------------------------------------------------
// g_cat = [g_x | g_ctx]  (float4 granularity). grid = NTOK*2048/4/256 = 8192
// ---------------------------------------------------------------------------
__global__ void cat_kernel() {
    int idx = blockIdx.x * blockDim.x + threadIdx.x;   // float4 index
    int row = idx >> 9;       // 512 float4 per row
    int c4  = idx & 511;
    float4 val = (c4 < 256) ? ((const float4*)g_x)[row * 256 + c4]
                            : ((const float4*)g_ctx)[row * 256 + (c4 - 256)];
    ((float4*)g_cat)[idx] = val;
}

// ---------------------------------------------------------------------------
// SGEMM: C = act(A[M,K] @ B[K,N] + bias[N])
// 128x128 block tile, BK=8, 256 threads, 8x8 per thread, register prefetch.
// Requires M%128==0, N%128==0, K%8==0 (true for all shapes here).
// EPI: 0=none 1=relu 2=tanh 3=sigmoid
// ---------------------------------------------------------------------------
template <int EPI>
__device__ __forceinline__ float epi_act(float x) {
    if (EPI == 1) return fmaxf(x, 0.f);
    if (EPI == 2) return tanhf(x);
    if (EPI == 3) return 1.f / (1.f + expf(-x));
    return x;
}

template <int EPI>
__global__ __launch_bounds__(256, 2)
void sgemm_kernel(const float* __restrict__ A, const float* __restrict__ B,
                  const float* __restrict__ bias, float* __restrict__ Cd,
                  int M, int N, int K) {
    __shared__ float As[8][128];
    __shared__ float Bs[8][128];

    const int tid = threadIdx.x;
    const int tx = tid & 15;    // 16 thread-cols
    const int ty = tid >> 4;    // 16 thread-rows

    const int rowBase = blockIdx.y * 128;
    const int colBase = blockIdx.x * 128;

    // global-load assignment
    const int aRow = tid >> 1;          // 0..127
    const int aK   = (tid & 1) << 2;    // 0 / 4
    const int bK   = tid >> 5;          // 0..7
    const int bCol = (tid & 31) << 2;   // 0..124

    const float* Ap = A + (size_t)(rowBase + aRow) * K + aK;
    const float* Bp = B + (size_t)bK * N + colBase + bCol;

    float4 aReg = *(const float4*)Ap;
    float4 bReg = *(const float4*)Bp;

    float acc[8][8];
    #pragma unroll
    for (int i = 0; i < 8; i++)
        #pragma unroll
        for (int j = 0; j < 8; j++) acc[i][j] = 0.f;

    const int nk = K >> 3;
    for (int kt = 0; kt < nk; kt++) {
        As[aK + 0][aRow] = aReg.x;
        As[aK + 1][aRow] = aReg.y;
        As[aK + 2][aRow] = aReg.z;
        As[aK + 3][aRow] = aReg.w;
        *(float4*)&Bs[bK][bCol] = bReg;
        __syncthreads();

        if (kt + 1 < nk) {
            Ap += 8;
            Bp += (size_t)8 * N;
            aReg = *(const float4*)Ap;
            bReg = *(const float4*)Bp;
        }

        #pragma unroll
        for (int kk = 0; kk < 8; kk++) {
            float4 a0 = *(const float4*)&As[kk][ty << 2];
            float4 a1 = *(const float4*)&As[kk][64 + (ty << 2)];
            float4 b0 = *(const float4*)&Bs[kk][tx << 2];
            float4 b1 = *(const float4*)&Bs[kk][64 + (tx << 2)];
            float av[8] = {a0.x, a0.y, a0.z, a0.w, a1.x, a1.y, a1.z, a1.w};
            float bv[8] = {b0.x, b0.y, b0.z, b0.w, b1.x, b1.y, b1.z, b1.w};
            #pragma unroll
            for (int i = 0; i < 8; i++)
                #pragma unroll
                for (int j = 0; j < 8; j++)
                    acc[i][j] = fmaf(av[i], bv[j], acc[i][j]);
        }
        __syncthreads();
    }

    // epilogue: bias + activation, float4 stores
    float4 bias0 = *(const float4*)(bias + colBase + (tx << 2));
    float4 bias1 = *(const float4*)(bias + colBase + 64 + (tx << 2));
    float bv8[8] = {bias0.x, bias0.y, bias0.z, bias0.w,
                    bias1.x, bias1.y, bias1.z, bias1.w};
    #pragma unroll
    for (int i = 0; i < 8; i++) {
        int r = rowBase + ((i < 4) ? ((ty << 2) + i) : (64 + (ty << 2) + i - 4));
        float* cp = Cd + (size_t)r * N + colBase;
        float4 o0, o1;
        o0.x = epi_act<EPI>(acc[i][0] + bv8[0]);
        o0.y = epi_act<EPI>(acc[i][1] + bv8[1]);
        o0.z = epi_act<EPI>(acc[i][2] + bv8[2]);
        o0.w = epi_act<EPI>(acc[i][3] + bv8[3]);
        o1.x = epi_act<EPI>(acc[i][4] + bv8[4]);
        o1.y = epi_act<EPI>(acc[i][5] + bv8[5]);
        o1.z = epi_act<EPI>(acc[i][6] + bv8[6]);
        o1.w = epi_act<EPI>(acc[i][7] + bv8[7]);
        *(float4*)(cp + (tx << 2)) = o0;
        *(float4*)(cp + 64 + (tx << 2)) = o1;
    }
}

// ---------------------------------------------------------------------------
// Launch
// ---------------------------------------------------------------------------
extern "C" void kernel_launch(void* const* d_in, const int* in_sizes, int n_in,
                              void* d_out, int out_size) {
    (void)in_sizes; (void)n_in; (void)out_size;

    const int*   ids  = (const int*)d_in[0];
    const float* tbl  = (const float*)d_in[1];
    const float* en_g = (const float*)d_in[2];
    const float* en_b = (const float*)d_in[3];
    const float* wA[2] = {(const float*)d_in[4],  (const float*)d_in[8]};
    const float* bA[2] = {(const float*)d_in[5],  (const float*)d_in[9]};
    const float* wB[2] = {(const float*)d_in[6],  (const float*)d_in[10]};
    const float* bB[2] = {(const float*)d_in[7],  (const float*)d_in[11]};
    const float* dw[2] = {(const float*)d_in[12], (const float*)d_in[20]};
    const float* db[2] = {(const float*)d_in[13], (const float*)d_in[21]};
    const float* fw[2] = {(const float*)d_in[14], (const float*)d_in[22]};
    const float* fb[2] = {(const float*)d_in[15], (const float*)d_in[23]};
    const float* iw[2] = {(const float*)d_in[16], (const float*)d_in[24]};
    const float* ib[2] = {(const float*)d_in[17], (const float*)d_in[25]};
    const float* cg[2] = {(const float*)d_in[18], (const float*)d_in[26]};
    const float* cb[2] = {(const float*)d_in[19], (const float*)d_in[27]};
    const float* ow = (const float*)d_in[28];
    const float* ob = (const float*)d_in[29];
    float* out = (float*)d_out;

    float *px, *pcat, *ph1, *ph2, *pdl, *pfg, *pig;
    cudaGetSymbolAddress((void**)&px,   g_x);
    cudaGetSymbolAddress((void**)&pcat, g_cat);
    cudaGetSymbolAddress((void**)&ph1,  g_h1);
    cudaGetSymbolAddress((void**)&ph2,  g_h2);
    cudaGetSymbolAddress((void**)&pdl,  g_dl);
    cudaGetSymbolAddress((void**)&pfg,  g_fg);
    cudaGetSymbolAddress((void**)&pig,  g_ig);

    zero_ctx_kernel<<<NTOK * CDIM / 4 / 256, 256>>>();
    embed_ln_kernel<<<NTOK, 256>>>(ids, tbl, en_g, en_b);

    for (int blk = 0; blk < 2; blk++) {
        cat_kernel<<<NTOK * (EDIM + CDIM) / 4 / 256, 256>>>();
        // h1 = relu(cat @ wA + bA)   [4096,2048]x[2048,4096]
        sgemm_kernel<1><<<dim3(HDIM / 128, NTOK / 128), 256>>>(
            pcat, wA[blk], bA[blk], ph1, NTOK, HDIM, EDIM + CDIM);
        // h2 = relu(h1 @ wB + bB)    [4096,4096]x[4096,4096]
        sgemm_kernel<1><<<dim3(HDIM / 128, NTOK / 128), 256>>>(
            ph1, wB[blk], bB[blk], ph2, NTOK, HDIM, HDIM);
        // gates                       [4096,4096]x[4096,1024]
        sgemm_kernel<2><<<dim3(CDIM / 128, NTOK / 128), 256>>>(
            ph2, dw[blk], db[blk], pdl, NTOK, CDIM, HDIM);
        sgemm_kernel<3><<<dim3(CDIM / 128, NTOK / 128), 256>>>(
            ph2, fw[blk], fb[blk], pfg, NTOK, CDIM, HDIM);
        sgemm_kernel<3><<<dim3(CDIM / 128, NTOK / 128), 256>>>(
            ph2, iw[blk], ib[blk], pig, NTOK, CDIM, HDIM);
        ctx_update_kernel<<<NTOK, 256>>>(cg[blk], cb[blk]);
    }

    // logits = h2 @ ow + ob          [4096,4096]x[4096,32000]
    sgemm_kernel<0><<<dim3(VDIM / 128, NTOK / 128), 256>>>(
        ph2, ow, ob, out, NTOK, VDIM, HDIM);
}

// round 3
// speedup vs baseline: 2.6851x; 2.6851x over previous
#include <cuda_runtime.h>
#include <cuda_bf16.h>
#include <cstdint>
#include <math.h>

#define NTOK 4096
#define EDIM 1024
#define CDIM 1024
#define HDIM 4096
#define VDIM 32000
#define EPS_LN 1e-5f

// ---------------------------------------------------------------------------
// Static scratch
// ---------------------------------------------------------------------------
__device__ float g_x[NTOK * EDIM];
__device__ float g_ctx[NTOK * CDIM];
__device__ float g_dl[NTOK * CDIM];
__device__ float g_fg[NTOK * CDIM];
__device__ float g_ig[NTOK * CDIM];

__device__ __nv_bfloat16 g_act_hi0[NTOK * HDIM];
__device__ __nv_bfloat16 g_act_lo0[NTOK * HDIM];
__device__ __nv_bfloat16 g_act_hi1[NTOK * HDIM];
__device__ __nv_bfloat16 g_act_lo1[NTOK * HDIM];

#define WT_TOTAL 206569472ULL
__device__ __nv_bfloat16 g_wt_hi[WT_TOTAL];
__device__ __nv_bfloat16 g_wt_lo[WT_TOTAL];

// ---------------------------------------------------------------------------
// helpers
// ---------------------------------------------------------------------------
__device__ __forceinline__ uint32_t smem_to_u32(const void* p) {
    uint32_t a;
    asm("{ .reg .u64 t; cvta.to.shared.u64 t, %1; cvt.u32.u64 %0, t; }"
        : "=r"(a) : "l"(p));
    return a;
}
__device__ __forceinline__ uint32_t swz(uint32_t o) { return o ^ ((o >> 3) & 0x70); }
__device__ __forceinline__ void cp_async16(uint32_t dst, const void* src) {
    asm volatile("cp.async.cg.shared.global [%0], [%1], 16;" :: "r"(dst), "l"(src));
}
template <int N>
__device__ __forceinline__ void cp_wait() {
    asm volatile("cp.async.wait_group %0;" :: "n"(N) : "memory");
}
__device__ __forceinline__ void cp_commit() {
    asm volatile("cp.async.commit_group;" ::: "memory");
}
__device__ __forceinline__ void ldsm_x4(uint32_t& a0, uint32_t& a1, uint32_t& a2,
                                        uint32_t& a3, uint32_t addr) {
    asm volatile("ldmatrix.sync.aligned.m8n8.x4.shared.b16 {%0,%1,%2,%3}, [%4];"
                 : "=r"(a0), "=r"(a1), "=r"(a2), "=r"(a3) : "r"(addr));
}
__device__ __forceinline__ void ldsm_x2(uint32_t& b0, uint32_t& b1, uint32_t addr) {
    asm volatile("ldmatrix.sync.aligned.m8n8.x2.shared.b16 {%0,%1}, [%2];"
                 : "=r"(b0), "=r"(b1) : "r"(addr));
}
__device__ __forceinline__ void mma_bf16(float& d0, float& d1, float& d2, float& d3,
                                         uint32_t a0, uint32_t a1, uint32_t a2, uint32_t a3,
                                         uint32_t b0, uint32_t b1) {
    asm volatile(
        "mma.sync.aligned.m16n8k16.row.col.f32.bf16.bf16.f32 "
        "{%0,%1,%2,%3}, {%4,%5,%6,%7}, {%8,%9}, {%0,%1,%2,%3};"
        : "+f"(d0), "+f"(d1), "+f"(d2), "+f"(d3)
        : "r"(a0), "r"(a1), "r"(a2), "r"(a3), "r"(b0), "r"(b1));
}

// ---------------------------------------------------------------------------
// small kernels
// ---------------------------------------------------------------------------
__device__ __forceinline__ float block_sum256(float val) {
    __shared__ float sh[8];
    int lane = threadIdx.x & 31;
    #pragma unroll
    for (int o = 16; o > 0; o >>= 1) val += __shfl_xor_sync(0xffffffffu, val, o);
    if (lane == 0) sh[threadIdx.x >> 5] = val;
    __syncthreads();
    float t = (lane < 8) ? sh[lane] : 0.f;
    #pragma unroll
    for (int o = 4; o > 0; o >>= 1) t += __shfl_xor_sync(0xffffffffu, t, o);
    t = __shfl_sync(0xffffffffu, t, 0);
    __syncthreads();
    return t;
}

__global__ void embed_ln_kernel(const int* __restrict__ ids,
                                const float* __restrict__ tbl,
                                const float* __restrict__ gw,
                                const float* __restrict__ gb) {
    int row = blockIdx.x;
    size_t base = (size_t)ids[row] * EDIM;
    float v[4];
    float s = 0.f;
    #pragma unroll
    for (int i = 0; i < 4; i++) { v[i] = tbl[base + threadIdx.x + i * 256]; s += v[i]; }
    float mean = block_sum256(s) * (1.f / (float)EDIM);
    float s2 = 0.f;
    #pragma unroll
    for (int i = 0; i < 4; i++) { float d = v[i] - mean; s2 += d * d; }
    float rstd = rsqrtf(block_sum256(s2) * (1.f / (float)EDIM) + EPS_LN);
    #pragma unroll
    for (int i = 0; i < 4; i++) {
        int c = threadIdx.x + i * 256;
        g_x[(size_t)row * EDIM + c] = (v[i] - mean) * rstd * gw[c] + gb[c];
    }
}

__global__ void ctx_update_kernel(const float* __restrict__ cg,
                                  const float* __restrict__ cb) {
    int row = blockIdx.x;
    size_t b = (size_t)row * CDIM;
    float v[4];
    float s = 0.f;
    #pragma unroll
    for (int i = 0; i < 4; i++) {
        int c = threadIdx.x + i * 256;
        v[i] = g_fg[b + c] * g_ctx[b + c] + g_ig[b + c] * g_dl[b + c];
        s += v[i];
    }
    float mean = block_sum256(s) * (1.f / (float)CDIM);
    float s2 = 0.f;
    #pragma unroll
    for (int i = 0; i < 4; i++) { float d = v[i] - mean; s2 += d * d; }
    float rstd = rsqrtf(block_sum256(s2) * (1.f / (float)CDIM) + EPS_LN);
    #pragma unroll
    for (int i = 0; i < 4; i++) {
        int c = threadIdx.x + i * 256;
        g_ctx[b + c] = (v[i] - mean) * rstd * cg[c] + cb[c];
    }
}

__global__ void zero_ctx_kernel() {
    int i = blockIdx.x * blockDim.x + threadIdx.x;
    ((float4*)g_ctx)[i] = make_float4(0.f, 0.f, 0.f, 0.f);
}

__device__ __forceinline__ void split2(float x0, float x1, uint32_t& hp, uint32_t& lp) {
    __nv_bfloat16 h0 = __float2bfloat16(x0), h1 = __float2bfloat16(x1);
    __nv_bfloat16 l0 = __float2bfloat16(x0 - __bfloat162float(h0));
    __nv_bfloat16 l1 = __float2bfloat16(x1 - __bfloat162float(h1));
    __nv_bfloat162 hh; hh.x = h0; hh.y = h1;
    __nv_bfloat162 ll; ll.x = l0; ll.y = l1;
    hp = *(uint32_t*)&hh; lp = *(uint32_t*)&ll;
}

__global__ void cat_split_kernel(__nv_bfloat16* __restrict__ hi,
                                 __nv_bfloat16* __restrict__ lo) {
    int idx = blockIdx.x * blockDim.x + threadIdx.x;
    int row = idx >> 9, c4 = idx & 511;
    float4 v = (c4 < 256) ? ((const float4*)g_x)[row * 256 + c4]
                          : ((const float4*)g_ctx)[row * 256 + (c4 - 256)];
    uint32_t hp0, lp0, hp1, lp1;
    split2(v.x, v.y, hp0, lp0);
    split2(v.z, v.w, hp1, lp1);
    *(uint2*)(hi + (size_t)row * 2048 + c4 * 4) = make_uint2(hp0, hp1);
    *(uint2*)(lo + (size_t)row * 2048 + c4 * 4) = make_uint2(lp0, lp1);
}

// W[K,N] fp32 -> Wt[N,K] hi/lo bf16
__global__ void wsplit_kernel(const float* __restrict__ W,
                              __nv_bfloat16* __restrict__ Thi,
                              __nv_bfloat16* __restrict__ Tlo, int K, int N) {
    __shared__ float t[32][33];
    int n0 = blockIdx.x << 5, k0 = blockIdx.y << 5;
    int tx = threadIdx.x & 31, ty = threadIdx.x >> 5;
    #pragma unroll
    for (int i = 0; i < 4; i++) {
        int kk = ty + i * 8;
        t[kk][tx] = W[(size_t)(k0 + kk) * N + n0 + tx];
    }
    __syncthreads();
    #pragma unroll
    for (int i = 0; i < 4; i++) {
        int nn = ty + i * 8;
        float v = t[tx][nn];
        __nv_bfloat16 h = __float2bfloat16(v);
        __nv_bfloat16 l = __float2bfloat16(v - __bfloat162float(h));
        size_t off = (size_t)(n0 + nn) * K + k0 + tx;
        Thi[off] = h; Tlo[off] = l;
    }
}

// ---------------------------------------------------------------------------
// mma.sync bf16x3 GEMM: C[M,N] = act(A @ W^T + bias)
// A split hi/lo [M,K]; W pre-transposed split hi/lo [N,K].
// Block tile 128x128, BK=64, 256 threads (8 warps, 2x4), warp tile 64x32.
// 2-stage cp.async pipeline. Stage: Ahi|Alo|Bhi|Blo each 128x64 bf16 (16KB).
// ---------------------------------------------------------------------------
#define STAGE_BYTES 65536
#define OFF_ALO 16384
#define OFF_BHI 32768
#define OFF_BLO 49152
#define GEMM_SMEM (2 * STAGE_BYTES)

template <int EPI>
__device__ __forceinline__ float epi_act(float x) {
    if (EPI == 1) return fmaxf(x, 0.f);
    if (EPI == 2) return tanhf(x);
    if (EPI == 3) return 1.f / (1.f + expf(-x));
    return x;
}

template <int EPI, int SPLIT>
__global__ void __launch_bounds__(256, 1)
gemm_mma3(const __nv_bfloat16* __restrict__ aHi, const __nv_bfloat16* __restrict__ aLo,
          const __nv_bfloat16* __restrict__ bHi, const __nv_bfloat16* __restrict__ bLo,
          const float* __restrict__ bias,
          float* __restrict__ outF,
          __nv_bfloat16* __restrict__ oHi, __nv_bfloat16* __restrict__ oLo,
          int N, int K) {
    extern __shared__ char smem[];
    const uint32_t sbase = smem_to_u32(smem);
    const int tid = threadIdx.x, wid = tid >> 5, lane = tid & 31;
    const int warp_m = wid & 1, warp_n = wid >> 1;
    const int rowBase = blockIdx.x * 128;
    const int colBase = blockIdx.y * 128;

    float acc[4][4][4];
    #pragma unroll
    for (int i = 0; i < 4; i++)
        #pragma unroll
        for (int j = 0; j < 4; j++)
            #pragma unroll
            for (int u = 0; u < 4; u++) acc[i][j][u] = 0.f;

    const int nk = K >> 6;

    // per-lane ldmatrix relative offsets
    const int aRow = warp_m * 64 + (lane & 15);        // + i*16
    const int aByte = (lane >> 4) << 4;                // 0/16
    const int bRow = warp_n * 32 + (lane & 7);         // + j*8
    const int bByte = ((lane >> 3) & 1) << 4;          // 0/16 (lanes 0-15 matter)

    // stage fill lambda-ish macro
    auto fill = [&](int kt) {
        const uint32_t st = sbase + (kt & 1) * STAGE_BYTES;
        const int k0 = kt << 6;
        #pragma unroll
        for (int i = 0; i < 16; i++) {
            int o = tid + (i << 8);
            int r = (o >> 3) & 127, c = o & 7;
            const __nv_bfloat16* src;
            uint32_t dst;
            if (o < 1024) {
                src = aHi + (size_t)(rowBase + r) * K + k0 + c * 8;
                dst = st + swz(r * 128 + c * 16);
            } else if (o < 2048) {
                src = aLo + (size_t)(rowBase + r) * K + k0 + c * 8;
                dst = st + OFF_ALO + swz(r * 128 + c * 16);
            } else if (o < 3072) {
                src = bHi + (size_t)(colBase + r) * K + k0 + c * 8;
                dst = st + OFF_BHI + swz(r * 128 + c * 16);
            } else {
                src = bLo + (size_t)(colBase + r) * K + k0 + c * 8;
                dst = st + OFF_BLO + swz(r * 128 + c * 16);
            }
            cp_async16(dst, src);
        }
        cp_commit();
    };

    fill(0);
    for (int kt = 0; kt < nk; kt++) {
        if (kt + 1 < nk) { fill(kt + 1); cp_wait<1>(); }
        else             { cp_wait<0>(); }
        __syncthreads();

        const uint32_t st = sbase + (kt & 1) * STAGE_BYTES;
        #pragma unroll
        for (int ks = 0; ks < 4; ks++) {
            uint32_t ah[4][4], al[4][4], bh[4][2], bl[4][2];
            #pragma unroll
            for (int i = 0; i < 4; i++)
                ldsm_x4(ah[i][0], ah[i][1], ah[i][2], ah[i][3],
                        st + swz((aRow + i * 16) * 128 + ks * 32 + aByte));
            #pragma unroll
            for (int j = 0; j < 4; j++)
                ldsm_x2(bh[j][0], bh[j][1],
                        st + OFF_BHI + swz((bRow + j * 8) * 128 + ks * 32 + bByte));
            #pragma unroll
            for (int i = 0; i < 4; i++)
                #pragma unroll
                for (int j = 0; j < 4; j++)
                    mma_bf16(acc[i][j][0], acc[i][j][1], acc[i][j][2], acc[i][j][3],
                             ah[i][0], ah[i][1], ah[i][2], ah[i][3], bh[j][0], bh[j][1]);
            #pragma unroll
            for (int j = 0; j < 4; j++)
                ldsm_x2(bl[j][0], bl[j][1],
                        st + OFF_BLO + swz((bRow + j * 8) * 128 + ks * 32 + bByte));
            #pragma unroll
            for (int i = 0; i < 4; i++)
                #pragma unroll
                for (int j = 0; j < 4; j++)
                    mma_bf16(acc[i][j][0], acc[i][j][1], acc[i][j][2], acc[i][j][3],
                             ah[i][0], ah[i][1], ah[i][2], ah[i][3], bl[j][0], bl[j][1]);
            #pragma unroll
            for (int i = 0; i < 4; i++)
                ldsm_x4(al[i][0], al[i][1], al[i][2], al[i][3],
                        st + OFF_ALO + swz((aRow + i * 16) * 128 + ks * 32 + aByte));
            #pragma unroll
            for (int i = 0; i < 4; i++)
                #pragma unroll
                for (int j = 0; j < 4; j++)
                    mma_bf16(acc[i][j][0], acc[i][j][1], acc[i][j][2], acc[i][j][3],
                             al[i][0], al[i][1], al[i][2], al[i][3], bh[j][0], bh[j][1]);
        }
        __syncthreads();
    }

    // epilogue
    const int erow = rowBase + warp_m * 64 + (lane >> 2);
    const int ecol = colBase + warp_n * 32 + (lane & 3) * 2;
    #pragma unroll
    for (int i = 0; i < 4; i++) {
        #pragma unroll
        for (int j = 0; j < 4; j++) {
            int col = ecol + j * 8;
            float b0 = bias[col], b1 = bias[col + 1];
            #pragma unroll
            for (int h = 0; h < 2; h++) {
                int r = erow + i * 16 + h * 8;
                float x0 = epi_act<EPI>(acc[i][j][2 * h + 0] + b0);
                float x1 = epi_act<EPI>(acc[i][j][2 * h + 1] + b1);
                if (SPLIT == 0) {
                    *(float2*)(outF + (size_t)r * N + col) = make_float2(x0, x1);
                } else {
                    uint32_t hp, lp;
                    split2(x0, x1, hp, lp);
                    *(uint32_t*)(oHi + (size_t)r * N + col) = hp;
                    *(uint32_t*)(oLo + (size_t)r * N + col) = lp;
                }
            }
        }
    }
}

// ---------------------------------------------------------------------------
// Launch
// ---------------------------------------------------------------------------
extern "C" void kernel_launch(void* const* d_in, const int* in_sizes, int n_in,
                              void* d_out, int out_size) {
    (void)in_sizes; (void)n_in; (void)out_size;

    const int*   ids  = (const int*)d_in[0];
    const float* tbl  = (const float*)d_in[1];
    const float* en_g = (const float*)d_in[2];
    const float* en_b = (const float*)d_in[3];
    const float* wA[2] = {(const float*)d_in[4],  (const float*)d_in[8]};
    const float* bA[2] = {(const float*)d_in[5],  (const float*)d_in[9]};
    const float* wB[2] = {(const float*)d_in[6],  (const float*)d_in[10]};
    const float* bB[2] = {(const float*)d_in[7],  (const float*)d_in[11]};
    const float* dw[2] = {(const float*)d_in[12], (const float*)d_in[20]};
    const float* db[2] = {(const float*)d_in[13], (const float*)d_in[21]};
    const float* fw[2] = {(const float*)d_in[14], (const float*)d_in[22]};
    const float* fb[2] = {(const float*)d_in[15], (const float*)d_in[23]};
    const float* iw[2] = {(const float*)d_in[16], (const float*)d_in[24]};
    const float* ib[2] = {(const float*)d_in[17], (const float*)d_in[25]};
    const float* cg[2] = {(const float*)d_in[18], (const float*)d_in[26]};
    const float* cb[2] = {(const float*)d_in[19], (const float*)d_in[27]};
    const float* ow = (const float*)d_in[28];
    const float* ob = (const float*)d_in[29];
    float* out = (float*)d_out;

    float *pdl, *pfg, *pig;
    __nv_bfloat16 *aHi[2], *aLo[2], *wtHi, *wtLo;
    cudaGetSymbolAddress((void**)&pdl,   g_dl);
    cudaGetSymbolAddress((void**)&pfg,   g_fg);
    cudaGetSymbolAddress((void**)&pig,   g_ig);
    cudaGetSymbolAddress((void**)&aHi[0], g_act_hi0);
    cudaGetSymbolAddress((void**)&aLo[0], g_act_lo0);
    cudaGetSymbolAddress((void**)&aHi[1], g_act_hi1);
    cudaGetSymbolAddress((void**)&aLo[1], g_act_lo1);
    cudaGetSymbolAddress((void**)&wtHi,  g_wt_hi);
    cudaGetSymbolAddress((void**)&wtLo,  g_wt_lo);

    cudaFuncSetAttribute(gemm_mma3<1, 1>, cudaFuncAttributeMaxDynamicSharedMemorySize, GEMM_SMEM);
    cudaFuncSetAttribute(gemm_mma3<2, 0>, cudaFuncAttributeMaxDynamicSharedMemorySize, GEMM_SMEM);
    cudaFuncSetAttribute(gemm_mma3<3, 0>, cudaFuncAttributeMaxDynamicSharedMemorySize, GEMM_SMEM);
    cudaFuncSetAttribute(gemm_mma3<0, 0>, cudaFuncAttributeMaxDynamicSharedMemorySize, GEMM_SMEM);

    const size_t OFF_WA[2] = {0,        37748736};
    const size_t OFF_WB[2] = {8388608,  46137344};
    const size_t OFF_DW[2] = {25165824, 62914560};
    const size_t OFF_FW[2] = {29360128, 67108864};
    const size_t OFF_IW[2] = {33554432, 71303168};
    const size_t OFF_OW = 75497472;

    zero_ctx_kernel<<<NTOK * CDIM / 4 / 256, 256>>>();
    embed_ln_kernel<<<NTOK, 256>>>(ids, tbl, en_g, en_b);

    for (int b = 0; b < 2; b++) {
        wsplit_kernel<<<dim3(HDIM / 32, (EDIM + CDIM) / 32), 256>>>(
            wA[b], wtHi + OFF_WA[b], wtLo + OFF_WA[b], EDIM + CDIM, HDIM);
        wsplit_kernel<<<dim3(HDIM / 32, HDIM / 32), 256>>>(
            wB[b], wtHi + OFF_WB[b], wtLo + OFF_WB[b], HDIM, HDIM);
        wsplit_kernel<<<dim3(CDIM / 32, HDIM / 32), 256>>>(
            dw[b], wtHi + OFF_DW[b], wtLo + OFF_DW[b], HDIM, CDIM);
        wsplit_kernel<<<dim3(CDIM / 32, HDIM / 32), 256>>>(
            fw[b], wtHi + OFF_FW[b], wtLo + OFF_FW[b], HDIM, CDIM);
        wsplit_kernel<<<dim3(CDIM / 32, HDIM / 32), 256>>>(
            iw[b], wtHi + OFF_IW[b], wtLo + OFF_IW[b], HDIM, CDIM);
    }
    wsplit_kernel<<<dim3(VDIM / 32, HDIM / 32), 256>>>(
        ow, wtHi + OFF_OW, wtLo + OFF_OW, HDIM, VDIM);

    for (int blk = 0; blk < 2; blk++) {
        int p = blk & 1;
        int q = 1 - p;
        cat_split_kernel<<<NTOK * (EDIM + CDIM) / 4 / 256, 256>>>(aHi[p], aLo[p]);
        gemm_mma3<1, 1><<<dim3(NTOK / 128, HDIM / 128), 256, GEMM_SMEM>>>(
            aHi[p], aLo[p], wtHi + OFF_WA[blk], wtLo + OFF_WA[blk], bA[blk],
            nullptr, aHi[q], aLo[q], HDIM, EDIM + CDIM);
        gemm_mma3<1, 1><<<dim3(NTOK / 128, HDIM / 128), 256, GEMM_SMEM>>>(
            aHi[q], aLo[q], wtHi + OFF_WB[blk], wtLo + OFF_WB[blk], bB[blk],
            nullptr, aHi[p], aLo[p], HDIM, HDIM);
        gemm_mma3<2, 0><<<dim3(NTOK / 128, CDIM / 128), 256, GEMM_SMEM>>>(
            aHi[p], aLo[p], wtHi + OFF_DW[blk], wtLo + OFF_DW[blk], db[blk],
            pdl, nullptr, nullptr, CDIM, HDIM);
        gemm_mma3<3, 0><<<dim3(NTOK / 128, CDIM / 128), 256, GEMM_SMEM>>>(
            aHi[p], aLo[p], wtHi + OFF_FW[blk], wtLo + OFF_FW[blk], fb[blk],
            pfg, nullptr, nullptr, CDIM, HDIM);
        gemm_mma3<3, 0><<<dim3(NTOK / 128, CDIM / 128), 256, GEMM_SMEM>>>(
            aHi[p], aLo[p], wtHi + OFF_IW[blk], wtLo + OFF_IW[blk], ib[blk],
            pig, nullptr, nullptr, CDIM, HDIM);
        ctx_update_kernel<<<NTOK, 256>>>(cg[blk], cb[blk]);
    }

    gemm_mma3<0, 0><<<dim3(NTOK / 128, VDIM / 128), 256, GEMM_SMEM>>>(
        aHi[1], aLo[1], wtHi + OFF_OW, wtLo + OFF_OW, ob,
        out, nullptr, nullptr, VDIM, HDIM);
}

// round 4
// speedup vs baseline: 2.7381x; 1.0198x over previous
#include <cuda_runtime.h>
#include <cuda_bf16.h>
#include <cstdint>
#include <math.h>

#define NTOK 4096
#define EDIM 1024
#define CDIM 1024
#define HDIM 4096
#define VDIM 32000
#define EPS_LN 1e-5f

// ---------------------------------------------------------------------------
// Static scratch
// ---------------------------------------------------------------------------
__device__ float g_x[NTOK * EDIM];
__device__ float g_ctx[NTOK * CDIM];
__device__ float g_dl[NTOK * CDIM];
__device__ float g_fg[NTOK * CDIM];
__device__ float g_ig[NTOK * CDIM];

__device__ __nv_bfloat16 g_act_hi0[NTOK * HDIM];
__device__ __nv_bfloat16 g_act_lo0[NTOK * HDIM];
__device__ __nv_bfloat16 g_act_hi1[NTOK * HDIM];
__device__ __nv_bfloat16 g_act_lo1[NTOK * HDIM];

#define WT_TOTAL 206569472ULL
__device__ __nv_bfloat16 g_wt_hi[WT_TOTAL];
__device__ __nv_bfloat16 g_wt_lo[WT_TOTAL];

// ---------------------------------------------------------------------------
// helpers
// ---------------------------------------------------------------------------
__device__ __forceinline__ uint32_t smem_to_u32(const void* p) {
    uint32_t a;
    asm("{ .reg .u64 t; cvta.to.shared.u64 t, %1; cvt.u32.u64 %0, t; }"
        : "=r"(a) : "l"(p));
    return a;
}
__device__ __forceinline__ uint32_t swz(uint32_t o) { return o ^ ((o >> 3) & 0x70); }
__device__ __forceinline__ void cp_async16(uint32_t dst, const void* src) {
    asm volatile("cp.async.cg.shared.global [%0], [%1], 16;" :: "r"(dst), "l"(src));
}
template <int N>
__device__ __forceinline__ void cp_wait() {
    asm volatile("cp.async.wait_group %0;" :: "n"(N) : "memory");
}
__device__ __forceinline__ void cp_commit() {
    asm volatile("cp.async.commit_group;" ::: "memory");
}
__device__ __forceinline__ void ldsm_x4(uint32_t& a0, uint32_t& a1, uint32_t& a2,
                                        uint32_t& a3, uint32_t addr) {
    asm volatile("ldmatrix.sync.aligned.m8n8.x4.shared.b16 {%0,%1,%2,%3}, [%4];"
                 : "=r"(a0), "=r"(a1), "=r"(a2), "=r"(a3) : "r"(addr));
}
__device__ __forceinline__ void mma_bf16(float& d0, float& d1, float& d2, float& d3,
                                         uint32_t a0, uint32_t a1, uint32_t a2, uint32_t a3,
                                         uint32_t b0, uint32_t b1) {
    asm volatile(
        "mma.sync.aligned.m16n8k16.row.col.f32.bf16.bf16.f32 "
        "{%0,%1,%2,%3}, {%4,%5,%6,%7}, {%8,%9}, {%0,%1,%2,%3};"
        : "+f"(d0), "+f"(d1), "+f"(d2), "+f"(d3)
        : "r"(a0), "r"(a1), "r"(a2), "r"(a3), "r"(b0), "r"(b1));
}

// ---------------------------------------------------------------------------
// small kernels
// ---------------------------------------------------------------------------
__device__ __forceinline__ float block_sum256(float val) {
    __shared__ float sh[8];
    int lane = threadIdx.x & 31;
    #pragma unroll
    for (int o = 16; o > 0; o >>= 1) val += __shfl_xor_sync(0xffffffffu, val, o);
    if (lane == 0) sh[threadIdx.x >> 5] = val;
    __syncthreads();
    float t = (lane < 8) ? sh[lane] : 0.f;
    #pragma unroll
    for (int o = 4; o > 0; o >>= 1) t += __shfl_xor_sync(0xffffffffu, t, o);
    t = __shfl_sync(0xffffffffu, t, 0);
    __syncthreads();
    return t;
}

__global__ void embed_ln_kernel(const int* __restrict__ ids,
                                const float* __restrict__ tbl,
                                const float* __restrict__ gw,
                                const float* __restrict__ gb) {
    int row = blockIdx.x;
    size_t base = (size_t)ids[row] * EDIM;
    float v[4];
    float s = 0.f;
    #pragma unroll
    for (int i = 0; i < 4; i++) { v[i] = tbl[base + threadIdx.x + i * 256]; s += v[i]; }
    float mean = block_sum256(s) * (1.f / (float)EDIM);
    float s2 = 0.f;
    #pragma unroll
    for (int i = 0; i < 4; i++) { float d = v[i] - mean; s2 += d * d; }
    float rstd = rsqrtf(block_sum256(s2) * (1.f / (float)EDIM) + EPS_LN);
    #pragma unroll
    for (int i = 0; i < 4; i++) {
        int c = threadIdx.x + i * 256;
        g_x[(size_t)row * EDIM + c] = (v[i] - mean) * rstd * gw[c] + gb[c];
    }
}

__global__ void ctx_update_kernel(const float* __restrict__ cg,
                                  const float* __restrict__ cb) {
    int row = blockIdx.x;
    size_t b = (size_t)row * CDIM;
    float v[4];
    float s = 0.f;
    #pragma unroll
    for (int i = 0; i < 4; i++) {
        int c = threadIdx.x + i * 256;
        v[i] = g_fg[b + c] * g_ctx[b + c] + g_ig[b + c] * g_dl[b + c];
        s += v[i];
    }
    float mean = block_sum256(s) * (1.f / (float)CDIM);
    float s2 = 0.f;
    #pragma unroll
    for (int i = 0; i < 4; i++) { float d = v[i] - mean; s2 += d * d; }
    float rstd = rsqrtf(block_sum256(s2) * (1.f / (float)CDIM) + EPS_LN);
    #pragma unroll
    for (int i = 0; i < 4; i++) {
        int c = threadIdx.x + i * 256;
        g_ctx[b + c] = (v[i] - mean) * rstd * cg[c] + cb[c];
    }
}

__global__ void zero_ctx_kernel() {
    int i = blockIdx.x * blockDim.x + threadIdx.x;
    ((float4*)g_ctx)[i] = make_float4(0.f, 0.f, 0.f, 0.f);
}

__device__ __forceinline__ void split2(float x0, float x1, uint32_t& hp, uint32_t& lp) {
    __nv_bfloat16 h0 = __float2bfloat16(x0), h1 = __float2bfloat16(x1);
    __nv_bfloat16 l0 = __float2bfloat16(x0 - __bfloat162float(h0));
    __nv_bfloat16 l1 = __float2bfloat16(x1 - __bfloat162float(h1));
    __nv_bfloat162 hh; hh.x = h0; hh.y = h1;
    __nv_bfloat162 ll; ll.x = l0; ll.y = l1;
    hp = *(uint32_t*)&hh; lp = *(uint32_t*)&ll;
}

__global__ void cat_split_kernel(__nv_bfloat16* __restrict__ hi,
                                 __nv_bfloat16* __restrict__ lo) {
    int idx = blockIdx.x * blockDim.x + threadIdx.x;
    int row = idx >> 9, c4 = idx & 511;
    float4 v = (c4 < 256) ? ((const float4*)g_x)[row * 256 + c4]
                          : ((const float4*)g_ctx)[row * 256 + (c4 - 256)];
    uint32_t hp0, lp0, hp1, lp1;
    split2(v.x, v.y, hp0, lp0);
    split2(v.z, v.w, hp1, lp1);
    *(uint2*)(hi + (size_t)row * 2048 + c4 * 4) = make_uint2(hp0, hp1);
    *(uint2*)(lo + (size_t)row * 2048 + c4 * 4) = make_uint2(lp0, lp1);
}

// ---------------------------------------------------------------------------
// Fused weight conversion: all 11 weights, one launch.
// W[K,N] fp32 -> Wt[N,K] hi/lo bf16 (tiled 32x32 transpose).
// ---------------------------------------------------------------------------
struct WJobs {
    const float* W[11];
    long long off[11];
    int K[11];
    int N[11];
    int start[12];
};

__global__ void wsplit_all_kernel(WJobs jobs,
                                  __nv_bfloat16* __restrict__ Thi,
                                  __nv_bfloat16* __restrict__ Tlo) {
    __shared__ float t[32][33];
    int b = blockIdx.x;
    int ji = 0;
    #pragma unroll
    for (int j = 0; j < 11; j++) if (b >= jobs.start[j + 1]) ji = j + 1;
    const float* W = jobs.W[ji];
    const int K = jobs.K[ji], N = jobs.N[ji];
    const long long off = jobs.off[ji];
    int tno = b - jobs.start[ji];
    int ntiles = N >> 5;
    int n0 = (tno % ntiles) << 5, k0 = (tno / ntiles) << 5;
    int tx = threadIdx.x & 31, ty = threadIdx.x >> 5;
    #pragma unroll
    for (int i = 0; i < 4; i++) {
        int kk = ty + i * 8;
        t[kk][tx] = W[(size_t)(k0 + kk) * N + n0 + tx];
    }
    __syncthreads();
    #pragma unroll
    for (int i = 0; i < 4; i++) {
        int nn = ty + i * 8;
        float v = t[tx][nn];
        __nv_bfloat16 h = __float2bfloat16(v);
        __nv_bfloat16 l = __float2bfloat16(v - __bfloat162float(h));
        size_t o = (size_t)off + (size_t)(n0 + nn) * K + k0 + tx;
        Thi[o] = h; Tlo[o] = l;
    }
}

// ---------------------------------------------------------------------------
// mma.sync bf16x3 GEMM: C[M,N] = act(A @ W^T + bias)
// Block tile 128x256, BK=64, 256 threads (8 warps as 2x4), warp tile 64x64.
// Stage: Ahi|Alo (128x64 each, 16KB) + Bhi|Blo (256x64 each, 32KB) = 96KB.
// 2-stage cp.async pipeline (192KB smem).
// ---------------------------------------------------------------------------
#define STAGE_BYTES 98304
#define OFF_ALO 16384
#define OFF_BHI 32768
#define OFF_BLO 65536
#define GEMM_SMEM (2 * STAGE_BYTES)

template <int EPI>
__device__ __forceinline__ float epi_act(float x) {
    if (EPI == 1) return fmaxf(x, 0.f);
    if (EPI == 2) return tanhf(x);
    if (EPI == 3) return 1.f / (1.f + expf(-x));
    return x;
}

template <int EPI, int SPLIT>
__global__ void __launch_bounds__(256, 1)
gemm_mma3(const __nv_bfloat16* __restrict__ aHi, const __nv_bfloat16* __restrict__ aLo,
          const __nv_bfloat16* __restrict__ bHi, const __nv_bfloat16* __restrict__ bLo,
          const float* __restrict__ bias,
          float* __restrict__ outF,
          __nv_bfloat16* __restrict__ oHi, __nv_bfloat16* __restrict__ oLo,
          int N, int K) {
    extern __shared__ char smem[];
    const uint32_t sbase = smem_to_u32(smem);
    const int tid = threadIdx.x, wid = tid >> 5, lane = tid & 31;
    const int warp_m = wid & 1, warp_n = wid >> 1;
    const int rowBase = blockIdx.x * 128;
    const int colBase = blockIdx.y * 256;

    float acc[4][8][4];
    #pragma unroll
    for (int i = 0; i < 4; i++)
        #pragma unroll
        for (int j = 0; j < 8; j++)
            #pragma unroll
            for (int u = 0; u < 4; u++) acc[i][j][u] = 0.f;

    const int nk = K >> 6;

    // ldmatrix lane addressing
    const int aRow = warp_m * 64 + (lane & 15);            // + i*16
    const int aByte = (lane >> 4) << 4;                    // 0/16
    const int bRow = warp_n * 64 + ((lane >> 4) << 3) + (lane & 7);  // + jj*16
    const int bByte = ((lane >> 3) & 1) << 4;              // 0/16

    auto fill = [&](int kt) {
        const uint32_t st = sbase + (kt & 1) * STAGE_BYTES;
        const int k0 = kt << 6;
        #pragma unroll
        for (int i = 0; i < 24; i++) {
            int o = tid + (i << 8);
            const __nv_bfloat16* src;
            uint32_t dst;
            if (o < 1024) {
                int r = o >> 3, c = o & 7;
                src = aHi + (size_t)(rowBase + r) * K + k0 + c * 8;
                dst = st + swz(r * 128 + c * 16);
            } else if (o < 2048) {
                int q = o - 1024, r = q >> 3, c = q & 7;
                src = aLo + (size_t)(rowBase + r) * K + k0 + c * 8;
                dst = st + OFF_ALO + swz(r * 128 + c * 16);
            } else if (o < 4096) {
                int q = o - 2048, r = q >> 3, c = q & 7;
                src = bHi + (size_t)(colBase + r) * K + k0 + c * 8;
                dst = st + OFF_BHI + swz(r * 128 + c * 16);
            } else {
                int q = o - 4096, r = q >> 3, c = q & 7;
                src = bLo + (size_t)(colBase + r) * K + k0 + c * 8;
                dst = st + OFF_BLO + swz(r * 128 + c * 16);
            }
            cp_async16(dst, src);
        }
        cp_commit();
    };

    fill(0);
    for (int kt = 0; kt < nk; kt++) {
        if (kt + 1 < nk) { fill(kt + 1); cp_wait<1>(); }
        else             { cp_wait<0>(); }
        __syncthreads();

        const uint32_t st = sbase + (kt & 1) * STAGE_BYTES;
        #pragma unroll
        for (int ks = 0; ks < 4; ks++) {
            uint32_t ah[4][4], bh[8][2];
            // A-hi fragments (4x m16k16)
            #pragma unroll
            for (int i = 0; i < 4; i++)
                ldsm_x4(ah[i][0], ah[i][1], ah[i][2], ah[i][3],
                        st + swz((aRow + i * 16) * 128 + ks * 32 + aByte));
            // B-hi fragments (8x n8k16 via 4x ldsm.x4)
            #pragma unroll
            for (int jj = 0; jj < 4; jj++)
                ldsm_x4(bh[2 * jj][0], bh[2 * jj][1], bh[2 * jj + 1][0], bh[2 * jj + 1][1],
                        st + OFF_BHI + swz((bRow + jj * 16) * 128 + ks * 32 + bByte));
            // pass 1: hi * hi
            #pragma unroll
            for (int i = 0; i < 4; i++)
                #pragma unroll
                for (int j = 0; j < 8; j++)
                    mma_bf16(acc[i][j][0], acc[i][j][1], acc[i][j][2], acc[i][j][3],
                             ah[i][0], ah[i][1], ah[i][2], ah[i][3], bh[j][0], bh[j][1]);
            // pass 2: lo * hi (al transient)
            {
                uint32_t al[4][4];
                #pragma unroll
                for (int i = 0; i < 4; i++)
                    ldsm_x4(al[i][0], al[i][1], al[i][2], al[i][3],
                            st + OFF_ALO + swz((aRow + i * 16) * 128 + ks * 32 + aByte));
                #pragma unroll
                for (int i = 0; i < 4; i++)
                    #pragma unroll
                    for (int j = 0; j < 8; j++)
                        mma_bf16(acc[i][j][0], acc[i][j][1], acc[i][j][2], acc[i][j][3],
                                 al[i][0], al[i][1], al[i][2], al[i][3], bh[j][0], bh[j][1]);
            }
            // pass 3: hi * lo (bl transient)
            {
                uint32_t bl[8][2];
                #pragma unroll
                for (int jj = 0; jj < 4; jj++)
                    ldsm_x4(bl[2 * jj][0], bl[2 * jj][1], bl[2 * jj + 1][0], bl[2 * jj + 1][1],
                            st + OFF_BLO + swz((bRow + jj * 16) * 128 + ks * 32 + bByte));
                #pragma unroll
                for (int i = 0; i < 4; i++)
                    #pragma unroll
                    for (int j = 0; j < 8; j++)
                        mma_bf16(acc[i][j][0], acc[i][j][1], acc[i][j][2], acc[i][j][3],
                                 ah[i][0], ah[i][1], ah[i][2], ah[i][3], bl[j][0], bl[j][1]);
            }
        }
        __syncthreads();
    }

    // epilogue
    const int erow = rowBase + warp_m * 64 + (lane >> 2);
    const int ecol = colBase + warp_n * 64 + (lane & 3) * 2;
    #pragma unroll
    for (int i = 0; i < 4; i++) {
        #pragma unroll
        for (int j = 0; j < 8; j++) {
            int col = ecol + j * 8;
            float b0 = bias[col], b1 = bias[col + 1];
            #pragma unroll
            for (int h = 0; h < 2; h++) {
                int r = erow + i * 16 + h * 8;
                float x0 = epi_act<EPI>(acc[i][j][2 * h + 0] + b0);
                float x1 = epi_act<EPI>(acc[i][j][2 * h + 1] + b1);
                if (SPLIT == 0) {
                    *(float2*)(outF + (size_t)r * N + col) = make_float2(x0, x1);
                } else {
                    uint32_t hp, lp;
                    split2(x0, x1, hp, lp);
                    *(uint32_t*)(oHi + (size_t)r * N + col) = hp;
                    *(uint32_t*)(oLo + (size_t)r * N + col) = lp;
                }
            }
        }
    }
}

// ---------------------------------------------------------------------------
// Launch
// ---------------------------------------------------------------------------
extern "C" void kernel_launch(void* const* d_in, const int* in_sizes, int n_in,
                              void* d_out, int out_size) {
    (void)in_sizes; (void)n_in; (void)out_size;

    const int*   ids  = (const int*)d_in[0];
    const float* tbl  = (const float*)d_in[1];
    const float* en_g = (const float*)d_in[2];
    const float* en_b = (const float*)d_in[3];
    const float* wA[2] = {(const float*)d_in[4],  (const float*)d_in[8]};
    const float* bA[2] = {(const float*)d_in[5],  (const float*)d_in[9]};
    const float* wB[2] = {(const float*)d_in[6],  (const float*)d_in[10]};
    const float* bB[2] = {(const float*)d_in[7],  (const float*)d_in[11]};
    const float* dw[2] = {(const float*)d_in[12], (const float*)d_in[20]};
    const float* db[2] = {(const float*)d_in[13], (const float*)d_in[21]};
    const float* fw[2] = {(const float*)d_in[14], (const float*)d_in[22]};
    const float* fb[2] = {(const float*)d_in[15], (const float*)d_in[23]};
    const float* iw[2] = {(const float*)d_in[16], (const float*)d_in[24]};
    const float* ib[2] = {(const float*)d_in[17], (const float*)d_in[25]};
    const float* cg[2] = {(const float*)d_in[18], (const float*)d_in[26]};
    const float* cb[2] = {(const float*)d_in[19], (const float*)d_in[27]};
    const float* ow = (const float*)d_in[28];
    const float* ob = (const float*)d_in[29];
    float* out = (float*)d_out;

    float *pdl, *pfg, *pig;
    __nv_bfloat16 *aHi[2], *aLo[2], *wtHi, *wtLo;
    cudaGetSymbolAddress((void**)&pdl,   g_dl);
    cudaGetSymbolAddress((void**)&pfg,   g_fg);
    cudaGetSymbolAddress((void**)&pig,   g_ig);
    cudaGetSymbolAddress((void**)&aHi[0], g_act_hi0);
    cudaGetSymbolAddress((void**)&aLo[0], g_act_lo0);
    cudaGetSymbolAddress((void**)&aHi[1], g_act_hi1);
    cudaGetSymbolAddress((void**)&aLo[1], g_act_lo1);
    cudaGetSymbolAddress((void**)&wtHi,  g_wt_hi);
    cudaGetSymbolAddress((void**)&wtLo,  g_wt_lo);

    cudaFuncSetAttribute(gemm_mma3<1, 1>, cudaFuncAttributeMaxDynamicSharedMemorySize, GEMM_SMEM);
    cudaFuncSetAttribute(gemm_mma3<2, 0>, cudaFuncAttributeMaxDynamicSharedMemorySize, GEMM_SMEM);
    cudaFuncSetAttribute(gemm_mma3<3, 0>, cudaFuncAttributeMaxDynamicSharedMemorySize, GEMM_SMEM);
    cudaFuncSetAttribute(gemm_mma3<0, 0>, cudaFuncAttributeMaxDynamicSharedMemorySize, GEMM_SMEM);

    const size_t OFF_WA[2] = {0,        37748736};
    const size_t OFF_WB[2] = {8388608,  46137344};
    const size_t OFF_DW[2] = {25165824, 62914560};
    const size_t OFF_FW[2] = {29360128, 67108864};
    const size_t OFF_IW[2] = {33554432, 71303168};
    const size_t OFF_OW = 75497472;

    zero_ctx_kernel<<<NTOK * CDIM / 4 / 256, 256>>>();
    embed_ln_kernel<<<NTOK, 256>>>(ids, tbl, en_g, en_b);

    // Fused weight conversion (single launch)
    {
        WJobs jobs;
        const float* ws[11] = {wA[0], wB[0], dw[0], fw[0], iw[0],
                               wA[1], wB[1], dw[1], fw[1], iw[1], ow};
        const size_t offs[11] = {OFF_WA[0], OFF_WB[0], OFF_DW[0], OFF_FW[0], OFF_IW[0],
                                 OFF_WA[1], OFF_WB[1], OFF_DW[1], OFF_FW[1], OFF_IW[1], OFF_OW};
        const int Ks[11] = {EDIM + CDIM, HDIM, HDIM, HDIM, HDIM,
                            EDIM + CDIM, HDIM, HDIM, HDIM, HDIM, HDIM};
        const int Ns[11] = {HDIM, HDIM, CDIM, CDIM, CDIM,
                            HDIM, HDIM, CDIM, CDIM, CDIM, VDIM};
        int cum = 0;
        for (int j = 0; j < 11; j++) {
            jobs.W[j] = ws[j];
            jobs.off[j] = (long long)offs[j];
            jobs.K[j] = Ks[j];
            jobs.N[j] = Ns[j];
            jobs.start[j] = cum;
            cum += (Ns[j] >> 5) * (Ks[j] >> 5);
        }
        jobs.start[11] = cum;
        wsplit_all_kernel<<<cum, 256>>>(jobs, wtHi, wtLo);
    }

    for (int blk = 0; blk < 2; blk++) {
        int p = blk & 1;
        int q = 1 - p;
        cat_split_kernel<<<NTOK * (EDIM + CDIM) / 4 / 256, 256>>>(aHi[p], aLo[p]);
        gemm_mma3<1, 1><<<dim3(NTOK / 128, HDIM / 256), 256, GEMM_SMEM>>>(
            aHi[p], aLo[p], wtHi + OFF_WA[blk], wtLo + OFF_WA[blk], bA[blk],
            nullptr, aHi[q], aLo[q], HDIM, EDIM + CDIM);
        gemm_mma3<1, 1><<<dim3(NTOK / 128, HDIM / 256), 256, GEMM_SMEM>>>(
            aHi[q], aLo[q], wtHi + OFF_WB[blk], wtLo + OFF_WB[blk], bB[blk],
            nullptr, aHi[p], aLo[p], HDIM, HDIM);
        gemm_mma3<2, 0><<<dim3(NTOK / 128, CDIM / 256), 256, GEMM_SMEM>>>(
            aHi[p], aLo[p], wtHi + OFF_DW[blk], wtLo + OFF_DW[blk], db[blk],
            pdl, nullptr, nullptr, CDIM, HDIM);
        gemm_mma3<3, 0><<<dim3(NTOK / 128, CDIM / 256), 256, GEMM_SMEM>>>(
            aHi[p], aLo[p], wtHi + OFF_FW[blk], wtLo + OFF_FW[blk], fb[blk],
            pfg, nullptr, nullptr, CDIM, HDIM);
        gemm_mma3<3, 0><<<dim3(NTOK / 128, CDIM / 256), 256, GEMM_SMEM>>>(
            aHi[p], aLo[p], wtHi + OFF_IW[blk], wtLo + OFF_IW[blk], ib[blk],
            pig, nullptr, nullptr, CDIM, HDIM);
        ctx_update_kernel<<<NTOK, 256>>>(cg[blk], cb[blk]);
    }

    gemm_mma3<0, 0><<<dim3(NTOK / 128, VDIM / 256), 256, GEMM_SMEM>>>(
        aHi[1], aLo[1], wtHi + OFF_OW, wtLo + OFF_OW, ob,
        out, nullptr, nullptr, VDIM, HDIM);
}

// round 5
// speedup vs baseline: 3.9833x; 1.4548x over previous
#include <cuda_runtime.h>
#include <cuda_fp16.h>
#include <cstdint>
#include <math.h>

#define NTOK 4096
#define EDIM 1024
#define CDIM 1024
#define HDIM 4096
#define VDIM 32000
#define EPS_LN 1e-5f

// ---------------------------------------------------------------------------
// Static scratch
// ---------------------------------------------------------------------------
__device__ float g_x[NTOK * EDIM];
__device__ float g_ctx[NTOK * CDIM];
__device__ float g_dl[NTOK * CDIM];
__device__ float g_fg[NTOK * CDIM];
__device__ float g_ig[NTOK * CDIM];

// activation ping-pong buffers, split hi/lo fp16
__device__ __half g_act_hi0[NTOK * HDIM];
__device__ __half g_act_lo0[NTOK * HDIM];
__device__ __half g_act_hi1[NTOK * HDIM];
__device__ __half g_act_lo1[NTOK * HDIM];

// transposed weights, single fp16 limb
#define WT_TOTAL 206569472ULL
__device__ __half g_wt[WT_TOTAL];

// ---------------------------------------------------------------------------
// helpers
// ---------------------------------------------------------------------------
__device__ __forceinline__ uint32_t smem_to_u32(const void* p) {
    uint32_t a;
    asm("{ .reg .u64 t; cvta.to.shared.u64 t, %1; cvt.u32.u64 %0, t; }"
        : "=r"(a) : "l"(p));
    return a;
}
__device__ __forceinline__ uint32_t swz(uint32_t o) { return o ^ ((o >> 3) & 0x70); }
__device__ __forceinline__ void cp_async16(uint32_t dst, const void* src) {
    asm volatile("cp.async.cg.shared.global [%0], [%1], 16;" :: "r"(dst), "l"(src));
}
template <int N>
__device__ __forceinline__ void cp_wait() {
    asm volatile("cp.async.wait_group %0;" :: "n"(N) : "memory");
}
__device__ __forceinline__ void cp_commit() {
    asm volatile("cp.async.commit_group;" ::: "memory");
}
__device__ __forceinline__ void ldsm_x4(uint32_t& a0, uint32_t& a1, uint32_t& a2,
                                        uint32_t& a3, uint32_t addr) {
    asm volatile("ldmatrix.sync.aligned.m8n8.x4.shared.b16 {%0,%1,%2,%3}, [%4];"
                 : "=r"(a0), "=r"(a1), "=r"(a2), "=r"(a3) : "r"(addr));
}
__device__ __forceinline__ void mma_f16(float& d0, float& d1, float& d2, float& d3,
                                        uint32_t a0, uint32_t a1, uint32_t a2, uint32_t a3,
                                        uint32_t b0, uint32_t b1) {
    asm volatile(
        "mma.sync.aligned.m16n8k16.row.col.f32.f16.f16.f32 "
        "{%0,%1,%2,%3}, {%4,%5,%6,%7}, {%8,%9}, {%0,%1,%2,%3};"
        : "+f"(d0), "+f"(d1), "+f"(d2), "+f"(d3)
        : "r"(a0), "r"(a1), "r"(a2), "r"(a3), "r"(b0), "r"(b1));
}

// ---------------------------------------------------------------------------
// small kernels
// ---------------------------------------------------------------------------
__device__ __forceinline__ float block_sum256(float val) {
    __shared__ float sh[8];
    int lane = threadIdx.x & 31;
    #pragma unroll
    for (int o = 16; o > 0; o >>= 1) val += __shfl_xor_sync(0xffffffffu, val, o);
    if (lane == 0) sh[threadIdx.x >> 5] = val;
    __syncthreads();
    float t = (lane < 8) ? sh[lane] : 0.f;
    #pragma unroll
    for (int o = 4; o > 0; o >>= 1) t += __shfl_xor_sync(0xffffffffu, t, o);
    t = __shfl_sync(0xffffffffu, t, 0);
    __syncthreads();
    return t;
}

__global__ void embed_ln_kernel(const int* __restrict__ ids,
                                const float* __restrict__ tbl,
                                const float* __restrict__ gw,
                                const float* __restrict__ gb) {
    int row = blockIdx.x;
    size_t base = (size_t)ids[row] * EDIM;
    float v[4];
    float s = 0.f;
    #pragma unroll
    for (int i = 0; i < 4; i++) { v[i] = tbl[base + threadIdx.x + i * 256]; s += v[i]; }
    float mean = block_sum256(s) * (1.f / (float)EDIM);
    float s2 = 0.f;
    #pragma unroll
    for (int i = 0; i < 4; i++) { float d = v[i] - mean; s2 += d * d; }
    float rstd = rsqrtf(block_sum256(s2) * (1.f / (float)EDIM) + EPS_LN);
    #pragma unroll
    for (int i = 0; i < 4; i++) {
        int c = threadIdx.x + i * 256;
        g_x[(size_t)row * EDIM + c] = (v[i] - mean) * rstd * gw[c] + gb[c];
    }
}

__global__ void ctx_update_kernel(const float* __restrict__ cg,
                                  const float* __restrict__ cb) {
    int row = blockIdx.x;
    size_t b = (size_t)row * CDIM;
    float v[4];
    float s = 0.f;
    #pragma unroll
    for (int i = 0; i < 4; i++) {
        int c = threadIdx.x + i * 256;
        v[i] = g_fg[b + c] * g_ctx[b + c] + g_ig[b + c] * g_dl[b + c];
        s += v[i];
    }
    float mean = block_sum256(s) * (1.f / (float)CDIM);
    float s2 = 0.f;
    #pragma unroll
    for (int i = 0; i < 4; i++) { float d = v[i] - mean; s2 += d * d; }
    float rstd = rsqrtf(block_sum256(s2) * (1.f / (float)CDIM) + EPS_LN);
    #pragma unroll
    for (int i = 0; i < 4; i++) {
        int c = threadIdx.x + i * 256;
        g_ctx[b + c] = (v[i] - mean) * rstd * cg[c] + cb[c];
    }
}

__global__ void zero_ctx_kernel() {
    int i = blockIdx.x * blockDim.x + threadIdx.x;
    ((float4*)g_ctx)[i] = make_float4(0.f, 0.f, 0.f, 0.f);
}

// fp16 hi/lo split of two floats, packed
__device__ __forceinline__ void split2h(float x0, float x1, uint32_t& hp, uint32_t& lp) {
    __half h0 = __float2half(x0), h1 = __float2half(x1);
    __half l0 = __float2half(x0 - __half2float(h0));
    __half l1 = __float2half(x1 - __half2float(h1));
    __half2 hh; hh.x = h0; hh.y = h1;
    __half2 ll; ll.x = l0; ll.y = l1;
    hp = *(uint32_t*)&hh; lp = *(uint32_t*)&ll;
}

__global__ void cat_split_kernel(__half* __restrict__ hi, __half* __restrict__ lo) {
    int idx = blockIdx.x * blockDim.x + threadIdx.x;
    int row = idx >> 9, c4 = idx & 511;
    float4 v = (c4 < 256) ? ((const float4*)g_x)[row * 256 + c4]
                          : ((const float4*)g_ctx)[row * 256 + (c4 - 256)];
    uint32_t hp0, lp0, hp1, lp1;
    split2h(v.x, v.y, hp0, lp0);
    split2h(v.z, v.w, hp1, lp1);
    *(uint2*)(hi + (size_t)row * 2048 + c4 * 4) = make_uint2(hp0, hp1);
    *(uint2*)(lo + (size_t)row * 2048 + c4 * 4) = make_uint2(lp0, lp1);
}

// ---------------------------------------------------------------------------
// Fused weight conversion: W[K,N] fp32 -> Wt[N,K] fp16 (single limb)
// ---------------------------------------------------------------------------
struct WJobs {
    const float* W[11];
    long long off[11];
    int K[11];
    int N[11];
    int start[12];
};

__global__ void wsplit_all_kernel(WJobs jobs, __half* __restrict__ T) {
    __shared__ float t[32][33];
    int b = blockIdx.x;
    int ji = 0;
    #pragma unroll
    for (int j = 0; j < 11; j++) if (b >= jobs.start[j + 1]) ji = j + 1;
    const float* W = jobs.W[ji];
    const int K = jobs.K[ji], N = jobs.N[ji];
    const long long off = jobs.off[ji];
    int tno = b - jobs.start[ji];
    int ntiles = N >> 5;
    int n0 = (tno % ntiles) << 5, k0 = (tno / ntiles) << 5;
    int tx = threadIdx.x & 31, ty = threadIdx.x >> 5;
    #pragma unroll
    for (int i = 0; i < 4; i++) {
        int kk = ty + i * 8;
        t[kk][tx] = W[(size_t)(k0 + kk) * N + n0 + tx];
    }
    __syncthreads();
    #pragma unroll
    for (int i = 0; i < 4; i++) {
        int nn = ty + i * 8;
        T[(size_t)off + (size_t)(n0 + nn) * K + k0 + tx] = __float2half(t[tx][nn]);
    }
}

// ---------------------------------------------------------------------------
// mma.sync fp16x2 GEMM: C[M,N] = act(A @ W^T + bias)
// A split hi/lo fp16 [M,K]; W single fp16 limb, pre-transposed [N,K].
// Block tile 128x256, BK=64, 256 threads (8 warps as 2x4), warp tile 64x64.
// Stage: Ahi|Alo (128x64 each, 16KB) + B (256x64, 32KB) = 64KB.
// 3-stage cp.async pipeline (192KB smem).
// Two MMA passes per k-step: ah*b + al*b.
// ---------------------------------------------------------------------------
#define STAGE_BYTES 65536
#define OFF_ALO 16384
#define OFF_B 32768
#define GEMM_SMEM (3 * STAGE_BYTES)

template <int EPI>
__device__ __forceinline__ float epi_act(float x) {
    if (EPI == 1) return fmaxf(x, 0.f);
    if (EPI == 2) return tanhf(x);
    if (EPI == 3) return 1.f / (1.f + expf(-x));
    return x;
}

template <int EPI, int SPLIT>
__global__ void __launch_bounds__(256, 1)
gemm_f16x2(const __half* __restrict__ aHi, const __half* __restrict__ aLo,
           const __half* __restrict__ bW,
           const float* __restrict__ bias,
           float* __restrict__ outF,
           __half* __restrict__ oHi, __half* __restrict__ oLo,
           int N, int K) {
    extern __shared__ char smem[];
    const uint32_t sbase = smem_to_u32(smem);
    const int tid = threadIdx.x, wid = tid >> 5, lane = tid & 31;
    const int warp_m = wid & 1, warp_n = wid >> 1;
    const int rowBase = blockIdx.x * 128;
    const int colBase = blockIdx.y * 256;

    float acc[4][8][4];
    #pragma unroll
    for (int i = 0; i < 4; i++)
        #pragma unroll
        for (int j = 0; j < 8; j++)
            #pragma unroll
            for (int u = 0; u < 4; u++) acc[i][j][u] = 0.f;

    const int nk = K >> 6;

    const int aRow = warp_m * 64 + (lane & 15);
    const int aByte = (lane >> 4) << 4;
    const int bRow = warp_n * 64 + ((lane >> 4) << 3) + (lane & 7);
    const int bByte = ((lane >> 3) & 1) << 4;

    auto fill = [&](int kt) {
        const uint32_t st = sbase + (kt % 3) * STAGE_BYTES;
        const int k0 = kt << 6;
        #pragma unroll
        for (int i = 0; i < 16; i++) {
            int o = tid + (i << 8);
            const __half* src;
            uint32_t dst;
            if (o < 1024) {
                int r = o >> 3, c = o & 7;
                src = aHi + (size_t)(rowBase + r) * K + k0 + c * 8;
                dst = st + swz(r * 128 + c * 16);
            } else if (o < 2048) {
                int q = o - 1024, r = q >> 3, c = q & 7;
                src = aLo + (size_t)(rowBase + r) * K + k0 + c * 8;
                dst = st + OFF_ALO + swz(r * 128 + c * 16);
            } else {
                int q = o - 2048, r = q >> 3, c = q & 7;
                src = bW + (size_t)(colBase + r) * K + k0 + c * 8;
                dst = st + OFF_B + swz(r * 128 + c * 16);
            }
            cp_async16(dst, src);
        }
        cp_commit();
    };

    fill(0);
    fill(1);
    for (int kt = 0; kt < nk; kt++) {
        if (kt + 1 < nk) cp_wait<1>();
        else             cp_wait<0>();
        __syncthreads();
        if (kt + 2 < nk) fill(kt + 2);

        const uint32_t st = sbase + (kt % 3) * STAGE_BYTES;
        #pragma unroll
        for (int ks = 0; ks < 4; ks++) {
            uint32_t ah[4][4], bh[8][2];
            #pragma unroll
            for (int i = 0; i < 4; i++)
                ldsm_x4(ah[i][0], ah[i][1], ah[i][2], ah[i][3],
                        st + swz((aRow + i * 16) * 128 + ks * 32 + aByte));
            #pragma unroll
            for (int jj = 0; jj < 4; jj++)
                ldsm_x4(bh[2 * jj][0], bh[2 * jj][1], bh[2 * jj + 1][0], bh[2 * jj + 1][1],
                        st + OFF_B + swz((bRow + jj * 16) * 128 + ks * 32 + bByte));
            // pass 1: a_hi * b
            #pragma unroll
            for (int i = 0; i < 4; i++)
                #pragma unroll
                for (int j = 0; j < 8; j++)
                    mma_f16(acc[i][j][0], acc[i][j][1], acc[i][j][2], acc[i][j][3],
                            ah[i][0], ah[i][1], ah[i][2], ah[i][3], bh[j][0], bh[j][1]);
            // pass 2: a_lo * b
            {
                uint32_t al[4][4];
                #pragma unroll
                for (int i = 0; i < 4; i++)
                    ldsm_x4(al[i][0], al[i][1], al[i][2], al[i][3],
                            st + OFF_ALO + swz((aRow + i * 16) * 128 + ks * 32 + aByte));
                #pragma unroll
                for (int i = 0; i < 4; i++)
                    #pragma unroll
                    for (int j = 0; j < 8; j++)
                        mma_f16(acc[i][j][0], acc[i][j][1], acc[i][j][2], acc[i][j][3],
                                al[i][0], al[i][1], al[i][2], al[i][3], bh[j][0], bh[j][1]);
            }
        }
        __syncthreads();
    }

    // epilogue
    const int erow = rowBase + warp_m * 64 + (lane >> 2);
    const int ecol = colBase + warp_n * 64 + (lane & 3) * 2;
    #pragma unroll
    for (int i = 0; i < 4; i++) {
        #pragma unroll
        for (int j = 0; j < 8; j++) {
            int col = ecol + j * 8;
            float b0 = bias[col], b1 = bias[col + 1];
            #pragma unroll
            for (int h = 0; h < 2; h++) {
                int r = erow + i * 16 + h * 8;
                float x0 = epi_act<EPI>(acc[i][j][2 * h + 0] + b0);
                float x1 = epi_act<EPI>(acc[i][j][2 * h + 1] + b1);
                if (SPLIT == 0) {
                    *(float2*)(outF + (size_t)r * N + col) = make_float2(x0, x1);
                } else {
                    uint32_t hp, lp;
                    split2h(x0, x1, hp, lp);
                    *(uint32_t*)(oHi + (size_t)r * N + col) = hp;
                    *(uint32_t*)(oLo + (size_t)r * N + col) = lp;
                }
            }
        }
    }
}

// ---------------------------------------------------------------------------
// Launch
// ---------------------------------------------------------------------------
extern "C" void kernel_launch(void* const* d_in, const int* in_sizes, int n_in,
                              void* d_out, int out_size) {
    (void)in_sizes; (void)n_in; (void)out_size;

    const int*   ids  = (const int*)d_in[0];
    const float* tbl  = (const float*)d_in[1];
    const float* en_g = (const float*)d_in[2];
    const float* en_b = (const float*)d_in[3];
    const float* wA[2] = {(const float*)d_in[4],  (const float*)d_in[8]};
    const float* bA[2] = {(const float*)d_in[5],  (const float*)d_in[9]};
    const float* wB[2] = {(const float*)d_in[6],  (const float*)d_in[10]};
    const float* bB[2] = {(const float*)d_in[7],  (const float*)d_in[11]};
    const float* dw[2] = {(const float*)d_in[12], (const float*)d_in[20]};
    const float* db[2] = {(const float*)d_in[13], (const float*)d_in[21]};
    const float* fw[2] = {(const float*)d_in[14], (const float*)d_in[22]};
    const float* fb[2] = {(const float*)d_in[15], (const float*)d_in[23]};
    const float* iw[2] = {(const float*)d_in[16], (const float*)d_in[24]};
    const float* ib[2] = {(const float*)d_in[17], (const float*)d_in[25]};
    const float* cg[2] = {(const float*)d_in[18], (const float*)d_in[26]};
    const float* cb[2] = {(const float*)d_in[19], (const float*)d_in[27]};
    const float* ow = (const float*)d_in[28];
    const float* ob = (const float*)d_in[29];
    float* out = (float*)d_out;

    float *pdl, *pfg, *pig;
    __half *aHi[2], *aLo[2], *wt;
    cudaGetSymbolAddress((void**)&pdl,   g_dl);
    cudaGetSymbolAddress((void**)&pfg,   g_fg);
    cudaGetSymbolAddress((void**)&pig,   g_ig);
    cudaGetSymbolAddress((void**)&aHi[0], g_act_hi0);
    cudaGetSymbolAddress((void**)&aLo[0], g_act_lo0);
    cudaGetSymbolAddress((void**)&aHi[1], g_act_hi1);
    cudaGetSymbolAddress((void**)&aLo[1], g_act_lo1);
    cudaGetSymbolAddress((void**)&wt,    g_wt);

    cudaFuncSetAttribute(gemm_f16x2<1, 1>, cudaFuncAttributeMaxDynamicSharedMemorySize, GEMM_SMEM);
    cudaFuncSetAttribute(gemm_f16x2<2, 0>, cudaFuncAttributeMaxDynamicSharedMemorySize, GEMM_SMEM);
    cudaFuncSetAttribute(gemm_f16x2<3, 0>, cudaFuncAttributeMaxDynamicSharedMemorySize, GEMM_SMEM);
    cudaFuncSetAttribute(gemm_f16x2<0, 0>, cudaFuncAttributeMaxDynamicSharedMemorySize, GEMM_SMEM);

    const size_t OFF_WA[2] = {0,        37748736};
    const size_t OFF_WB[2] = {8388608,  46137344};
    const size_t OFF_DW[2] = {25165824, 62914560};
    const size_t OFF_FW[2] = {29360128, 67108864};
    const size_t OFF_IW[2] = {33554432, 71303168};
    const size_t OFF_OW = 75497472;

    zero_ctx_kernel<<<NTOK * CDIM / 4 / 256, 256>>>();
    embed_ln_kernel<<<NTOK, 256>>>(ids, tbl, en_g, en_b);

    {
        WJobs jobs;
        const float* ws[11] = {wA[0], wB[0], dw[0], fw[0], iw[0],
                               wA[1], wB[1], dw[1], fw[1], iw[1], ow};
        const size_t offs[11] = {OFF_WA[0], OFF_WB[0], OFF_DW[0], OFF_FW[0], OFF_IW[0],
                                 OFF_WA[1], OFF_WB[1], OFF_DW[1], OFF_FW[1], OFF_IW[1], OFF_OW};
        const int Ks[11] = {EDIM + CDIM, HDIM, HDIM, HDIM, HDIM,
                            EDIM + CDIM, HDIM, HDIM, HDIM, HDIM, HDIM};
        const int Ns[11] = {HDIM, HDIM, CDIM, CDIM, CDIM,
                            HDIM, HDIM, CDIM, CDIM, CDIM, VDIM};
        int cum = 0;
        for (int j = 0; j < 11; j++) {
            jobs.W[j] = ws[j];
            jobs.off[j] = (long long)offs[j];
            jobs.K[j] = Ks[j];
            jobs.N[j] = Ns[j];
            jobs.start[j] = cum;
            cum += (Ns[j] >> 5) * (Ks[j] >> 5);
        }
        jobs.start[11] = cum;
        wsplit_all_kernel<<<cum, 256>>>(jobs, wt);
    }

    for (int blk = 0; blk < 2; blk++) {
        int p = blk & 1;
        int q = 1 - p;
        cat_split_kernel<<<NTOK * (EDIM + CDIM) / 4 / 256, 256>>>(aHi[p], aLo[p]);
        gemm_f16x2<1, 1><<<dim3(NTOK / 128, HDIM / 256), 256, GEMM_SMEM>>>(
            aHi[p], aLo[p], wt + OFF_WA[blk], bA[blk],
            nullptr, aHi[q], aLo[q], HDIM, EDIM + CDIM);
        gemm_f16x2<1, 1><<<dim3(NTOK / 128, HDIM / 256), 256, GEMM_SMEM>>>(
            aHi[q], aLo[q], wt + OFF_WB[blk], bB[blk],
            nullptr, aHi[p], aLo[p], HDIM, HDIM);
        gemm_f16x2<2, 0><<<dim3(NTOK / 128, CDIM / 256), 256, GEMM_SMEM>>>(
            aHi[p], aLo[p], wt + OFF_DW[blk], db[blk],
            pdl, nullptr, nullptr, CDIM, HDIM);
        gemm_f16x2<3, 0><<<dim3(NTOK / 128, CDIM / 256), 256, GEMM_SMEM>>>(
            aHi[p], aLo[p], wt + OFF_FW[blk], fb[blk],
            pfg, nullptr, nullptr, CDIM, HDIM);
        gemm_f16x2<3, 0><<<dim3(NTOK / 128, CDIM / 256), 256, GEMM_SMEM>>>(
            aHi[p], aLo[p], wt + OFF_IW[blk], ib[blk],
            pig, nullptr, nullptr, CDIM, HDIM);
        ctx_update_kernel<<<NTOK, 256>>>(cg[blk], cb[blk]);
    }

    gemm_f16x2<0, 0><<<dim3(NTOK / 128, VDIM / 256), 256, GEMM_SMEM>>>(
        aHi[1], aLo[1], wt + OFF_OW, ob,
        out, nullptr, nullptr, VDIM, HDIM);
}